// round 10
// baseline (speedup 1.0000x reference)
#include <cuda_runtime.h>
#include <math.h>

// ---------------------------------------------------------------------------
// Fast helpers
// ---------------------------------------------------------------------------
__device__ __forceinline__ float sqrt_approx(float x) {
    float r;
    asm("sqrt.approx.f32 %0, %1;" : "=f"(r) : "f"(x));
    return r;
}
__device__ __forceinline__ float ex2_approx(float x) {
    float r;
    asm("ex2.approx.f32 %0, %1;" : "=f"(r) : "f"(x));
    return r;
}
__device__ __forceinline__ float lg2_approx(float x) {
    float r;
    asm("lg2.approx.f32 %0, %1;" : "=f"(r) : "f"(x));
    return r;
}

// ---------------------------------------------------------------------------
// sRGB -> Lab
// ---------------------------------------------------------------------------
__device__ __forceinline__ float srgb_inv(float x) {
    float u = (x + 0.055f) * (1.0f / 1.055f);
    float p = ex2_approx(2.4f * lg2_approx(u));
    return (x > 0.04045f) ? p : x * (1.0f / 12.92f);
}

__device__ __forceinline__ float lab_f(float t) {
    float p = ex2_approx((1.0f / 3.0f) * lg2_approx(fmaxf(t, 1e-8f)));
    return (t > 0.008856f) ? p : fmaf(7.787f, t, 4.0f / 29.0f);
}

__device__ __forceinline__ void rgb2lab(float r, float g, float b,
                                        float& L, float& A, float& B) {
    r = srgb_inv(r);
    g = srgb_inv(g);
    b = srgb_inv(b);
    float x = 0.412453f * r + 0.35758f  * g + 0.180423f * b;
    float y = 0.212671f * r + 0.71516f  * g + 0.072169f * b;
    float z = 0.019334f * r + 0.119193f * g + 0.950227f * b;
    float fx = lab_f(x * (1.0f / 0.95047f));
    float fy = lab_f(y);
    float fz = lab_f(z * (1.0f / 1.08883f));
    L = 116.0f * fy - 16.0f;
    A = 500.0f * (fx - fy);
    B = 200.0f * (fy - fz);
}

// ---------------------------------------------------------------------------
// CIEDE2000 (returns deltaE / 100)
//  - hue terms via vector identities (no per-image atan2 / sincos / wraps)
//  - T weighting as exact bivariate polynomial P(c) + s*Q(c)
//  - dtheta Gaussian via cos(H-275deg) series (no atan2 at all)
// ---------------------------------------------------------------------------
__device__ __forceinline__ float ciede2000_div100(float L1, float a1, float b1,
                                                  float L2, float a2, float b2) {
    const float K25_7 = 6103515625.0f;  // 25^7

    float C1 = sqrt_approx(fmaf(a1, a1, b1 * b1));
    float C2 = sqrt_approx(fmaf(a2, a2, b2 * b2));
    float Cbar = 0.5f * (C1 + C2);
    float cb2 = Cbar * Cbar;
    float cb4 = cb2 * cb2;
    float c7  = cb4 * cb2 * Cbar;
    float G = 0.5f * (1.0f - sqrt_approx(__fdividef(c7, c7 + K25_7)));
    float scale = 1.0f + G;

    float a1p = a1 * scale;
    float a2p = a2 * scale;
    float C1p = sqrt_approx(fmaf(a1p, a1p, b1 * b1));
    float C2p = sqrt_approx(fmaf(a2p, a2p, b2 * b2));

    // L term
    float Lbar = 0.5f * (L1 + L2);
    float lt = (Lbar - 50.0f) * (Lbar - 50.0f);
    float SL = 1.0f + 0.015f * lt * rsqrtf(20.0f + lt);
    float L_term = __fdividef(L2 - L1, SL);

    // C term
    float Cbarp = 0.5f * (C1p + C2p);
    float SC = fmaf(0.045f, Cbarp, 1.0f);
    float C_term = __fdividef(C2p - C1p, SC);

    // Hue difference term: dH_term = 2*sqrt(CC)*sin(dH/2)
    float CC    = C1p * C2p;
    float dot   = fmaf(a1p, a2p, b1 * b2);   // CC * cos(h2-h1)
    float cross = fmaf(a1p, b2, -b1 * a2p);  // CC * sin(h2-h1)
    float dH_term = copysignf(sqrt_approx(2.0f * fmaxf(CC - dot, 0.0f)), cross);

    // Mean hue direction (short-arc bisector), w = C2p*v1 + C1p*v2
    float wx = fmaf(C2p, a1p, C1p * a2p);
    float wy = fmaf(C2p, b1,  C1p * b2);
    float rs = rsqrtf(fmaxf(fmaf(wx, wx, wy * wy), 1e-30f));
    float cH = wx * rs;
    float sH = wy * rs;

    // T = P(cH) + sH*Q(cH)   (exact expansion of the 4-cosine sum)
    float P = fmaf(fmaf(fmaf(fmaf(-0.72638480f, cH, 1.27298803f), cH,
                             1.20638480f), cH, -1.10196534f), cH, 0.66920190f);
    float Q = fmaf(fmaf(fmaf(-1.42561044f, cH, -0.13379643f), cH,
                        0.71280522f), cH, -0.05155090f);
    float T = fmaf(sH, Q, P);

    float SH = fmaf(0.015f * Cbarp, T, 1.0f);
    float H_term = __fdividef(dH_term, SH);

    // Rotation term
    float cp2 = Cbarp * Cbarp;
    float cp4 = cp2 * cp2;
    float c7p = cp4 * cp2 * Cbarp;
    float Rc = 2.0f * sqrt_approx(__fdividef(c7p, c7p + K25_7));

    // dtheta = pi/6 * exp(-((Hdeg-275)/25)^2), via delta = H - 275deg:
    //   cos(delta) = cH*cos275 + sH*sin275
    //   delta^2    = 2u + u^2/3 + (4/45)u^3,  u = 1 - cos(delta)
    float cd = fmaf(cH, 0.08715574f, -0.99619470f * sH);
    float u  = 1.0f - cd;
    float dsq = u * fmaf(u, fmaf(u, 0.08888889f, 0.33333333f), 2.0f);
    // 2*dtheta = (pi/3) * exp(-5.25249*dsq);  exp via ex2: *log2(e)
    float twodt = 1.04719755f * ex2_approx(-7.57774f * dsq);
    float R_term = -__sinf(twodt) * Rc * C_term * H_term;

    float dE2 = fmaf(L_term, L_term,
               fmaf(C_term, C_term,
               fmaf(H_term, H_term, R_term)));
    return sqrt_approx(fmaxf(dE2, 0.0f)) * 0.01f;
}

// ---------------------------------------------------------------------------
// Kernel: one thread = 4 pixels (float4), layout (B, 3, H, W)
// ---------------------------------------------------------------------------
constexpr int PLANE = 512 * 512;       // H*W (power of two)
constexpr int IMG_STRIDE = 3 * PLANE;  // per-batch stride in elements

__global__ void __launch_bounds__(256)
ciede2000_kernel(const float4* __restrict__ im1,
                 const float4* __restrict__ im2,
                 float4* __restrict__ out,
                 int nq)
{
    int v = blockIdx.x * 256 + threadIdx.x;
    if (v >= nq) return;

    int p   = v << 2;
    int n   = p / PLANE;
    int pix = p - n * PLANE;
    int b4  = (n * IMG_STRIDE + pix) >> 2;
    const int c4 = PLANE >> 2;

    float4 r1 = im1[b4];
    float4 g1 = im1[b4 + c4];
    float4 u1 = im1[b4 + 2 * c4];
    float4 r2 = im2[b4];
    float4 g2 = im2[b4 + c4];
    float4 u2 = im2[b4 + 2 * c4];

    float R1[4] = {r1.x, r1.y, r1.z, r1.w};
    float G1[4] = {g1.x, g1.y, g1.z, g1.w};
    float B1[4] = {u1.x, u1.y, u1.z, u1.w};
    float R2[4] = {r2.x, r2.y, r2.z, r2.w};
    float G2[4] = {g2.x, g2.y, g2.z, g2.w};
    float B2[4] = {u2.x, u2.y, u2.z, u2.w};

    float o[4];
#pragma unroll
    for (int j = 0; j < 4; j++) {
        float L1, A1, Bb1, L2, A2, Bb2;
        rgb2lab(R1[j], G1[j], B1[j], L1, A1, Bb1);
        rgb2lab(R2[j], G2[j], B2[j], L2, A2, Bb2);
        o[j] = ciede2000_div100(L1, A1, Bb1, L2, A2, Bb2);
    }

    out[v] = make_float4(o[0], o[1], o[2], o[3]);
}

// ---------------------------------------------------------------------------
// Launch
// ---------------------------------------------------------------------------
extern "C" void kernel_launch(void* const* d_in, const int* in_sizes, int n_in,
                              void* d_out, int out_size) {
    const float4* im1 = (const float4*)d_in[0];
    const float4* im2 = (const float4*)d_in[1];
    float4* out = (float4*)d_out;

    int nq = out_size >> 2;
    int blocks = (nq + 255) / 256;
    ciede2000_kernel<<<blocks, 256>>>(im1, im2, out, nq);
}

// round 11
// speedup vs baseline: 1.0246x; 1.0246x over previous
#include <cuda_runtime.h>
#include <math.h>

// ---------------------------------------------------------------------------
// Fast helpers
// ---------------------------------------------------------------------------
__device__ __forceinline__ float sqrt_approx(float x) {
    float r;
    asm("sqrt.approx.f32 %0, %1;" : "=f"(r) : "f"(x));
    return r;
}
__device__ __forceinline__ float ex2_approx(float x) {
    float r;
    asm("ex2.approx.f32 %0, %1;" : "=f"(r) : "f"(x));
    return r;
}
__device__ __forceinline__ float lg2_approx(float x) {
    float r;
    asm("lg2.approx.f32 %0, %1;" : "=f"(r) : "f"(x));
    return r;
}

// ---------------------------------------------------------------------------
// sRGB -> Lab
// ---------------------------------------------------------------------------
__device__ __forceinline__ float srgb_inv(float x) {
    float u = (x + 0.055f) * (1.0f / 1.055f);
    float p = ex2_approx(2.4f * lg2_approx(u));
    return (x > 0.04045f) ? p : x * (1.0f / 12.92f);
}

__device__ __forceinline__ float lab_f(float t) {
    float p = ex2_approx((1.0f / 3.0f) * lg2_approx(fmaxf(t, 1e-8f)));
    return (t > 0.008856f) ? p : fmaf(7.787f, t, 4.0f / 29.0f);
}

__device__ __forceinline__ void rgb2lab(float r, float g, float b,
                                        float& L, float& A, float& B) {
    r = srgb_inv(r);
    g = srgb_inv(g);
    b = srgb_inv(b);
    float x = 0.412453f * r + 0.35758f  * g + 0.180423f * b;
    float y = 0.212671f * r + 0.71516f  * g + 0.072169f * b;
    float z = 0.019334f * r + 0.119193f * g + 0.950227f * b;
    float fx = lab_f(x * (1.0f / 0.95047f));
    float fy = lab_f(y);
    float fz = lab_f(z * (1.0f / 1.08883f));
    L = 116.0f * fy - 16.0f;
    A = 500.0f * (fx - fy);
    B = 200.0f * (fy - fz);
}

// ---------------------------------------------------------------------------
// CIEDE2000 (returns deltaE / 100)
//  - hue terms via vector identities (no per-image atan2 / sincos / wraps)
//  - T weighting as exact bivariate polynomial P(c) + s*Q(c)
//  - dtheta Gaussian via cos(H-275deg) series (no atan2 at all)
// ---------------------------------------------------------------------------
__device__ __forceinline__ float ciede2000_div100(float L1, float a1, float b1,
                                                  float L2, float a2, float b2) {
    const float K25_7 = 6103515625.0f;  // 25^7

    float C1 = sqrt_approx(fmaf(a1, a1, b1 * b1));
    float C2 = sqrt_approx(fmaf(a2, a2, b2 * b2));
    float Cbar = 0.5f * (C1 + C2);
    float cb2 = Cbar * Cbar;
    float cb4 = cb2 * cb2;
    float c7  = cb4 * cb2 * Cbar;
    float G = 0.5f * (1.0f - sqrt_approx(__fdividef(c7, c7 + K25_7)));
    float scale = 1.0f + G;

    float a1p = a1 * scale;
    float a2p = a2 * scale;
    float C1p = sqrt_approx(fmaf(a1p, a1p, b1 * b1));
    float C2p = sqrt_approx(fmaf(a2p, a2p, b2 * b2));

    // L term
    float Lbar = 0.5f * (L1 + L2);
    float lt = (Lbar - 50.0f) * (Lbar - 50.0f);
    float SL = 1.0f + 0.015f * lt * rsqrtf(20.0f + lt);
    float L_term = __fdividef(L2 - L1, SL);

    // C term
    float Cbarp = 0.5f * (C1p + C2p);
    float SC = fmaf(0.045f, Cbarp, 1.0f);
    float C_term = __fdividef(C2p - C1p, SC);

    // Hue difference term: dH_term = 2*sqrt(CC)*sin(dH/2)
    float CC    = C1p * C2p;
    float dot   = fmaf(a1p, a2p, b1 * b2);   // CC * cos(h2-h1)
    float cross = fmaf(a1p, b2, -b1 * a2p);  // CC * sin(h2-h1)
    float dH_term = copysignf(sqrt_approx(2.0f * fmaxf(CC - dot, 0.0f)), cross);

    // Mean hue direction (short-arc bisector), w = C2p*v1 + C1p*v2
    float wx = fmaf(C2p, a1p, C1p * a2p);
    float wy = fmaf(C2p, b1,  C1p * b2);
    float rs = rsqrtf(fmaxf(fmaf(wx, wx, wy * wy), 1e-30f));
    float cH = wx * rs;
    float sH = wy * rs;

    // T = P(cH) + sH*Q(cH)   (exact expansion of the 4-cosine sum)
    float P = fmaf(fmaf(fmaf(fmaf(-0.72638480f, cH, 1.27298803f), cH,
                             1.20638480f), cH, -1.10196534f), cH, 0.66920190f);
    float Q = fmaf(fmaf(fmaf(-1.42561044f, cH, -0.13379643f), cH,
                        0.71280522f), cH, -0.05155090f);
    float T = fmaf(sH, Q, P);

    float SH = fmaf(0.015f * Cbarp, T, 1.0f);
    float H_term = __fdividef(dH_term, SH);

    // Rotation term
    float cp2 = Cbarp * Cbarp;
    float cp4 = cp2 * cp2;
    float c7p = cp4 * cp2 * Cbarp;
    float Rc = 2.0f * sqrt_approx(__fdividef(c7p, c7p + K25_7));

    // dtheta = pi/6 * exp(-((Hdeg-275)/25)^2), via delta = H - 275deg:
    //   cos(delta) = cH*cos275 + sH*sin275
    //   delta^2    = 2u + u^2/3 + (4/45)u^3,  u = 1 - cos(delta)
    float cd = fmaf(cH, 0.08715574f, -0.99619470f * sH);
    float u  = 1.0f - cd;
    float dsq = u * fmaf(u, fmaf(u, 0.08888889f, 0.33333333f), 2.0f);
    // 2*dtheta = (pi/3) * exp(-5.25249*dsq);  exp via ex2: *log2(e)
    float twodt = 1.04719755f * ex2_approx(-7.57774f * dsq);
    float R_term = -__sinf(twodt) * Rc * C_term * H_term;

    float dE2 = fmaf(L_term, L_term,
               fmaf(C_term, C_term,
               fmaf(H_term, H_term, R_term)));
    return sqrt_approx(fmaxf(dE2, 0.0f)) * 0.01f;
}

// ---------------------------------------------------------------------------
// Kernel: one thread = 4 pixels (float4), layout (B, 3, H, W)
// ---------------------------------------------------------------------------
constexpr int PLANE = 512 * 512;       // H*W (power of two)
constexpr int IMG_STRIDE = 3 * PLANE;  // per-batch stride in elements

__global__ void __launch_bounds__(256)
ciede2000_kernel(const float4* __restrict__ im1,
                 const float4* __restrict__ im2,
                 float4* __restrict__ out,
                 int nq)
{
    int v = blockIdx.x * 256 + threadIdx.x;
    if (v >= nq) return;

    int p   = v << 2;
    int n   = p / PLANE;
    int pix = p - n * PLANE;
    int b4  = (n * IMG_STRIDE + pix) >> 2;
    const int c4 = PLANE >> 2;

    float4 r1 = im1[b4];
    float4 g1 = im1[b4 + c4];
    float4 u1 = im1[b4 + 2 * c4];
    float4 r2 = im2[b4];
    float4 g2 = im2[b4 + c4];
    float4 u2 = im2[b4 + 2 * c4];

    float R1[4] = {r1.x, r1.y, r1.z, r1.w};
    float G1[4] = {g1.x, g1.y, g1.z, g1.w};
    float B1[4] = {u1.x, u1.y, u1.z, u1.w};
    float R2[4] = {r2.x, r2.y, r2.z, r2.w};
    float G2[4] = {g2.x, g2.y, g2.z, g2.w};
    float B2[4] = {u2.x, u2.y, u2.z, u2.w};

    float o[4];
#pragma unroll
    for (int j = 0; j < 4; j++) {
        float L1, A1, Bb1, L2, A2, Bb2;
        rgb2lab(R1[j], G1[j], B1[j], L1, A1, Bb1);
        rgb2lab(R2[j], G2[j], B2[j], L2, A2, Bb2);
        o[j] = ciede2000_div100(L1, A1, Bb1, L2, A2, Bb2);
    }

    out[v] = make_float4(o[0], o[1], o[2], o[3]);
}

// ---------------------------------------------------------------------------
// Launch
// ---------------------------------------------------------------------------
extern "C" void kernel_launch(void* const* d_in, const int* in_sizes, int n_in,
                              void* d_out, int out_size) {
    const float4* im1 = (const float4*)d_in[0];
    const float4* im2 = (const float4*)d_in[1];
    float4* out = (float4*)d_out;

    int nq = out_size >> 2;
    int blocks = (nq + 255) / 256;
    ciede2000_kernel<<<blocks, 256>>>(im1, im2, out, nq);
}